// round 1
// baseline (speedup 1.0000x reference)
#include <cuda_runtime.h>
#include <math.h>

#define N_NODES 200000
#define N_EDGES 6400000
#define HPAD 52   // 50 floats padded to 52 -> 208B rows, 16B aligned

// Scratch (device globals: no allocation allowed in kernel_launch)
__device__ float g_h0s[(size_t)N_NODES * HPAD];  // dinv[src]-prescaled GCN features
__device__ float g_agg[(size_t)N_NODES * HPAD];  // edge-sum accumulator
__device__ float g_deg[N_NODES];                 // degree (incl. self loop)

// ---------------------------------------------------------------------------
// K0: zero agg, init deg = 1 (self loop)
// ---------------------------------------------------------------------------
__global__ void k_init() {
    long i = (long)blockIdx.x * blockDim.x + threadIdx.x;
    const long tot = (long)N_NODES * HPAD;
    if (i < tot) g_agg[i] = 0.0f;
    if (i < N_NODES) g_deg[i] = 1.0f;
}

// ---------------------------------------------------------------------------
// K1: degree accumulation over dst
// ---------------------------------------------------------------------------
__global__ void k_deg(const int* __restrict__ ei) {
    int e = blockIdx.x * blockDim.x + threadIdx.x;
    if (e < N_EDGES) atomicAdd(&g_deg[ei[N_EDGES + e]], 1.0f);
}

// ---------------------------------------------------------------------------
// K2: h0s[i] = (x[i,100:150] @ Wg^T) * rsqrt(deg[i])
// one thread per node; Wg (50x50) in shared
// ---------------------------------------------------------------------------
__global__ __launch_bounds__(128) void k_h0(const float* __restrict__ x,
                                            const float* __restrict__ Wg) {
    __shared__ float Ws[2500];
    for (int j = threadIdx.x; j < 2500; j += blockDim.x) Ws[j] = Wg[j];
    __syncthreads();
    int i = blockIdx.x * blockDim.x + threadIdx.x;
    if (i >= N_NODES) return;

    float xv[50];
    const float* xr = x + (size_t)i * 150 + 100;
#pragma unroll
    for (int k = 0; k < 50; k++) xv[k] = __ldg(&xr[k]);

    float dinv = rsqrtf(g_deg[i]);
    float* outr = g_h0s + (size_t)i * HPAD;
#pragma unroll
    for (int j = 0; j < 50; j++) {
        float acc = 0.0f;
#pragma unroll
        for (int k = 0; k < 50; k++) acc = fmaf(Ws[j * 50 + k], xv[k], acc);
        outr[j] = acc * dinv;
    }
}

// ---------------------------------------------------------------------------
// K3: edge scatter-add: agg[dst] += h0s[src]
// 16 threads per edge: lanes 0..11 do 16B vector reds, lane 12 does the 8B tail
// ---------------------------------------------------------------------------
__global__ __launch_bounds__(256) void k_edge(const int* __restrict__ ei) {
    long t = (long)blockIdx.x * blockDim.x + threadIdx.x;
    int e = (int)(t >> 4);
    if (e >= N_EDGES) return;
    int l = (int)(t & 15);
    int s = __ldg(&ei[e]);
    int d = __ldg(&ei[N_EDGES + e]);
    const float* hp = g_h0s + (size_t)s * HPAD;
    float* ap = g_agg + (size_t)d * HPAD;
    if (l < 12) {
        float4 v = *(const float4*)(hp + 4 * l);
        asm volatile("red.global.v4.f32.add [%0], {%1,%2,%3,%4};"
                     :: "l"(ap + 4 * l), "f"(v.x), "f"(v.y), "f"(v.z), "f"(v.w)
                     : "memory");
    } else if (l == 12) {
        float2 v = *(const float2*)(hp + 48);
        asm volatile("red.global.v2.f32.add [%0], {%1,%2};"
                     :: "l"(ap + 48), "f"(v.x), "f"(v.y)
                     : "memory");
    }
}

// ---------------------------------------------------------------------------
// K4: fused finalize + full VAE chain, one thread per node.
// h = dinv*(agg + h0s) + bg ; e1..e3 ; reparam ; z ; d1,d2 ; sigmoid out.
// All weights in shared (28.6 KB). All loops fully unrolled -> reg arrays.
// ---------------------------------------------------------------------------
__global__ __launch_bounds__(128) void k_dense(
    const float* __restrict__ eps,
    const float* __restrict__ bg,
    const float* __restrict__ We1, const float* __restrict__ be1,
    const float* __restrict__ We2, const float* __restrict__ be2,
    const float* __restrict__ We3, const float* __restrict__ be3,
    const float* __restrict__ Wfc, const float* __restrict__ bfc,
    const float* __restrict__ Wd1, const float* __restrict__ bd1,
    const float* __restrict__ Wd2, const float* __restrict__ bd2,
    const float* __restrict__ Wd3, const float* __restrict__ bd3,
    float* __restrict__ out)
{
    __shared__ float S[7160];
    float* sWe1 = S;               // 2000
    float* sWe2 = S + 2000;        // 1200
    float* sWe3 = S + 3200;        // 600
    float* sWfc = S + 3800;        // 100
    float* sWd1 = S + 3900;        // 200
    float* sWd2 = S + 4100;        // 800
    float* sWd3 = S + 4900;        // 2000
    float* sbg  = S + 6900;        // 50
    float* sbe1 = S + 6950;        // 40
    float* sbe2 = S + 6990;        // 30
    float* sbe3 = S + 7020;        // 20
    float* sbfc = S + 7040;        // 10
    float* sbd1 = S + 7050;        // 20
    float* sbd2 = S + 7070;        // 40
    float* sbd3 = S + 7110;        // 50

    int tid = threadIdx.x;
    for (int j = tid; j < 2000; j += 128) sWe1[j] = We1[j];
    for (int j = tid; j < 1200; j += 128) sWe2[j] = We2[j];
    for (int j = tid; j <  600; j += 128) sWe3[j] = We3[j];
    for (int j = tid; j <  100; j += 128) sWfc[j] = Wfc[j];
    for (int j = tid; j <  200; j += 128) sWd1[j] = Wd1[j];
    for (int j = tid; j <  800; j += 128) sWd2[j] = Wd2[j];
    for (int j = tid; j < 2000; j += 128) sWd3[j] = Wd3[j];
    if (tid < 50) sbg[tid]  = bg[tid];
    if (tid < 40) sbe1[tid] = be1[tid];
    if (tid < 30) sbe2[tid] = be2[tid];
    if (tid < 20) sbe3[tid] = be3[tid];
    if (tid < 10) sbfc[tid] = bfc[tid];
    if (tid < 20) sbd1[tid] = bd1[tid];
    if (tid < 40) sbd2[tid] = bd2[tid];
    if (tid < 50) sbd3[tid] = bd3[tid];
    __syncthreads();

    int i = blockIdx.x * 128 + tid;
    if (i >= N_NODES) return;

    float dinv = rsqrtf(g_deg[i]);
    const float* aggr = g_agg + (size_t)i * HPAD;
    const float* h0r  = g_h0s + (size_t)i * HPAD;

    float h[50];
#pragma unroll
    for (int j = 0; j < 50; j++) h[j] = fmaf(dinv, aggr[j] + h0r[j], sbg[j]);

    float e1[40];
#pragma unroll
    for (int j = 0; j < 40; j++) {
        float a = sbe1[j];
#pragma unroll
        for (int k = 0; k < 50; k++) a = fmaf(h[k], sWe1[j * 50 + k], a);
        e1[j] = (a >= 0.0f) ? a : 0.01f * a;
    }

    float e2[30];
#pragma unroll
    for (int j = 0; j < 30; j++) {
        float a = sbe2[j];
#pragma unroll
        for (int k = 0; k < 40; k++) a = fmaf(e1[k], sWe2[j * 40 + k], a);
        e2[j] = (a >= 0.0f) ? a : 0.01f * a;
    }

    float e3[20];
#pragma unroll
    for (int j = 0; j < 20; j++) {
        float a = sbe3[j];
#pragma unroll
        for (int k = 0; k < 30; k++) a = fmaf(e2[k], sWe3[j * 30 + k], a);
        e3[j] = a;  // no activation; e3[0:10]=mu, e3[10:20]=log_var
    }

    float z1[10];
#pragma unroll
    for (int j = 0; j < 10; j++)
        z1[j] = fmaf(__ldg(&eps[(size_t)i * 10 + j]), __expf(0.5f * e3[10 + j]), e3[j]);

    float z[10];
#pragma unroll
    for (int j = 0; j < 10; j++) {
        float a = sbfc[j];
#pragma unroll
        for (int k = 0; k < 10; k++) a = fmaf(z1[k], sWfc[j * 10 + k], a);
        z[j] = fmaxf(a, 0.0f);
    }

    float d1[20];
#pragma unroll
    for (int j = 0; j < 20; j++) {
        float a = sbd1[j];
#pragma unroll
        for (int k = 0; k < 10; k++) a = fmaf(z[k], sWd1[j * 10 + k], a);
        d1[j] = (a >= 0.0f) ? a : 0.01f * a;
    }

    float d2[40];
#pragma unroll
    for (int j = 0; j < 40; j++) {
        float a = sbd2[j];
#pragma unroll
        for (int k = 0; k < 20; k++) a = fmaf(d1[k], sWd2[j * 20 + k], a);
        d2[j] = (a >= 0.0f) ? a : 0.01f * a;
    }

    // outputs: [mu_prime (N,50)][mu (N,10)][log_var (N,10)][z (N,10)] flat
    float* mp = out + (size_t)i * 50;
#pragma unroll
    for (int j = 0; j < 50; j++) {
        float a = sbd3[j];
#pragma unroll
        for (int k = 0; k < 40; k++) a = fmaf(d2[k], sWd3[j * 40 + k], a);
        mp[j] = 1.0f / (1.0f + __expf(-a));
    }
    float* omu = out + (size_t)N_NODES * 50 + (size_t)i * 10;
    float* olv = out + (size_t)N_NODES * 60 + (size_t)i * 10;
    float* oz  = out + (size_t)N_NODES * 70 + (size_t)i * 10;
#pragma unroll
    for (int j = 0; j < 10; j++) {
        omu[j] = e3[j];
        olv[j] = e3[10 + j];
        oz[j]  = z[j];
    }
}

// ---------------------------------------------------------------------------
extern "C" void kernel_launch(void* const* d_in, const int* in_sizes, int n_in,
                              void* d_out, int out_size) {
    const float* x   = (const float*)d_in[0];
    const int*   ei  = (const int*)d_in[1];
    const float* eps = (const float*)d_in[2];
    const float* Wg  = (const float*)d_in[3];
    const float* bg  = (const float*)d_in[4];
    const float* We1 = (const float*)d_in[5];
    const float* be1 = (const float*)d_in[6];
    const float* We2 = (const float*)d_in[7];
    const float* be2 = (const float*)d_in[8];
    const float* We3 = (const float*)d_in[9];
    const float* be3 = (const float*)d_in[10];
    const float* Wfc = (const float*)d_in[11];
    const float* bfc = (const float*)d_in[12];
    const float* Wd1 = (const float*)d_in[13];
    const float* bd1 = (const float*)d_in[14];
    const float* Wd2 = (const float*)d_in[15];
    const float* bd2 = (const float*)d_in[16];
    const float* Wd3 = (const float*)d_in[17];
    const float* bd3 = (const float*)d_in[18];
    float* out = (float*)d_out;

    {   // K0 init
        long tot = (long)N_NODES * HPAD;
        int blocks = (int)((tot + 255) / 256);
        k_init<<<blocks, 256>>>();
    }
    {   // K1 degree
        int blocks = (N_EDGES + 255) / 256;
        k_deg<<<blocks, 256>>>(ei);
    }
    {   // K2 h0s
        int blocks = (N_NODES + 127) / 128;
        k_h0<<<blocks, 128>>>(x, Wg);
    }
    {   // K3 edge scatter
        long threads = (long)N_EDGES * 16;
        int blocks = (int)((threads + 255) / 256);
        k_edge<<<blocks, 256>>>(ei);
    }
    {   // K4 fused dense chain
        int blocks = (N_NODES + 127) / 128;
        k_dense<<<blocks, 128>>>(eps, bg, We1, be1, We2, be2, We3, be3,
                                 Wfc, bfc, Wd1, bd1, Wd2, bd2, Wd3, bd3, out);
    }
    (void)in_sizes; (void)n_in; (void)out_size;
}

// round 4
// speedup vs baseline: 1.4977x; 1.4977x over previous
#include <cuda_runtime.h>
#include <math.h>

#define N_NODES 200000
#define N_EDGES 6400000
#define HPAD 52            // 50 floats padded to 52 -> 208B rows, 16B aligned
#define SCAN_B 1024
#define NB_SCAN 196        // ceil(200000/1024)

// Scratch (device globals)
__device__ float g_h0s[(size_t)N_NODES * HPAD];  // dinv[src]-prescaled GCN features
__device__ float g_agg[(size_t)N_NODES * HPAD];  // gathered neighbor sums
__device__ int   g_cnt[N_NODES];                 // in-degree (excl self)
__device__ int   g_off[N_NODES];                 // scan offsets (mutated by fill -> inclusive)
__device__ int   g_bsums[NB_SCAN];
__device__ int   g_csr[N_EDGES];                 // src ids bucketed by dst

// ---------------------------------------------------------------------------
__global__ void k_zero() {
    int i = blockIdx.x * blockDim.x + threadIdx.x;
    if (i < N_NODES) g_cnt[i] = 0;
}

__global__ void k_count(const int* __restrict__ ei) {
    int e = blockIdx.x * blockDim.x + threadIdx.x;
    if (e < N_EDGES) atomicAdd(&g_cnt[__ldg(&ei[N_EDGES + e])], 1);
}

// ---- 3-kernel exclusive scan of g_cnt into g_off --------------------------
__global__ __launch_bounds__(SCAN_B) void k_scan1() {
    __shared__ int s[SCAN_B];
    int tid = threadIdx.x;
    int i = blockIdx.x * SCAN_B + tid;
    int v = (i < N_NODES) ? g_cnt[i] : 0;
    s[tid] = v;
    __syncthreads();
#pragma unroll
    for (int off = 1; off < SCAN_B; off <<= 1) {
        int t = (tid >= off) ? s[tid - off] : 0;
        __syncthreads();
        s[tid] += t;
        __syncthreads();
    }
    if (i < N_NODES) g_off[i] = s[tid] - v;      // exclusive
    if (tid == SCAN_B - 1) g_bsums[blockIdx.x] = s[tid];
}

__global__ __launch_bounds__(256) void k_scan2() {
    __shared__ int s[256];
    int tid = threadIdx.x;
    int v = (tid < NB_SCAN) ? g_bsums[tid] : 0;
    s[tid] = v;
    __syncthreads();
#pragma unroll
    for (int off = 1; off < 256; off <<= 1) {
        int t = (tid >= off) ? s[tid - off] : 0;
        __syncthreads();
        s[tid] += t;
        __syncthreads();
    }
    if (tid < NB_SCAN) g_bsums[tid] = s[tid] - v;  // exclusive
}

__global__ __launch_bounds__(SCAN_B) void k_scan3() {
    int i = blockIdx.x * SCAN_B + threadIdx.x;
    if (i < N_NODES) g_off[i] += g_bsums[blockIdx.x];
}

// ---- CSR fill: after this, g_off[i] = inclusive prefix (= end of bucket i)
__global__ void k_fill(const int* __restrict__ ei) {
    int e = blockIdx.x * blockDim.x + threadIdx.x;
    if (e >= N_EDGES) return;
    int s = __ldg(&ei[e]);
    int d = __ldg(&ei[N_EDGES + e]);
    int pos = atomicAdd(&g_off[d], 1);
    g_csr[pos] = s;
}

// ---------------------------------------------------------------------------
// h0s[i] = (x[i,100:150] @ Wg^T) * rsqrt(cnt[i]+1); x staged through shared
// ---------------------------------------------------------------------------
__global__ __launch_bounds__(128) void k_h0(const float* __restrict__ x,
                                            const float* __restrict__ Wg) {
    __shared__ float Ws[2500];
    __shared__ float sx[128 * 51];   // stride 51 -> conflict-free
    int tid = threadIdx.x;
    int base = blockIdx.x * 128;
    for (int j = tid; j < 2500; j += 128) Ws[j] = Wg[j];
    // cooperative coalesced load of x[:,100:150] for this block's 128 rows
    for (int idx = tid; idx < 128 * 50; idx += 128) {
        int r = idx / 50, k = idx - r * 50;
        float v = 0.0f;
        if (base + r < N_NODES) v = __ldg(&x[(size_t)(base + r) * 150 + 100 + k]);
        sx[r * 51 + k] = v;
    }
    __syncthreads();
    int i = base + tid;
    if (i >= N_NODES) return;

    const float* xv = sx + tid * 51;
    float dinv = rsqrtf((float)g_cnt[i] + 1.0f);
    float* outr = g_h0s + (size_t)i * HPAD;
    float res[50];
#pragma unroll
    for (int j = 0; j < 50; j++) {
        float acc = 0.0f;
#pragma unroll
        for (int k = 0; k < 50; k++) acc = fmaf(Ws[j * 50 + k], xv[k], acc);
        res[j] = acc * dinv;
    }
#pragma unroll
    for (int j4 = 0; j4 < 12; j4++)
        ((float4*)outr)[j4] = make_float4(res[4*j4], res[4*j4+1], res[4*j4+2], res[4*j4+3]);
    ((float2*)outr)[24] = make_float2(res[48], res[49]);
}

// ---------------------------------------------------------------------------
// Gather: 13 threads per node, each accumulating one float4 chunk over in-nbrs
// ---------------------------------------------------------------------------
__global__ __launch_bounds__(256) void k_gather() {
    int t = blockIdx.x * blockDim.x + threadIdx.x;
    int i = t / 13;
    if (i >= N_NODES) return;
    int c = t - i * 13;
    int start = (i == 0) ? 0 : __ldg(&g_off[i - 1]);
    int end = __ldg(&g_off[i]);

    float4 acc = make_float4(0.f, 0.f, 0.f, 0.f);
    const float* hb = g_h0s + 4 * c;
    int p = start;
    for (; p + 3 < end; p += 4) {
        int s0 = __ldg(&g_csr[p]);
        int s1 = __ldg(&g_csr[p + 1]);
        int s2 = __ldg(&g_csr[p + 2]);
        int s3 = __ldg(&g_csr[p + 3]);
        float4 v0 = *(const float4*)(hb + (size_t)s0 * HPAD);
        float4 v1 = *(const float4*)(hb + (size_t)s1 * HPAD);
        float4 v2 = *(const float4*)(hb + (size_t)s2 * HPAD);
        float4 v3 = *(const float4*)(hb + (size_t)s3 * HPAD);
        acc.x += v0.x + v1.x + v2.x + v3.x;
        acc.y += v0.y + v1.y + v2.y + v3.y;
        acc.z += v0.z + v1.z + v2.z + v3.z;
        acc.w += v0.w + v1.w + v2.w + v3.w;
    }
    for (; p < end; p++) {
        int s0 = __ldg(&g_csr[p]);
        float4 v0 = *(const float4*)(hb + (size_t)s0 * HPAD);
        acc.x += v0.x; acc.y += v0.y; acc.z += v0.z; acc.w += v0.w;
    }
    *(float4*)(g_agg + (size_t)i * HPAD + 4 * c) = acc;
}

// ---------------------------------------------------------------------------
// Fused finalize + full VAE chain, one thread per node.
// ---------------------------------------------------------------------------
__global__ __launch_bounds__(128) void k_dense(
    const float* __restrict__ eps,
    const float* __restrict__ bg,
    const float* __restrict__ We1, const float* __restrict__ be1,
    const float* __restrict__ We2, const float* __restrict__ be2,
    const float* __restrict__ We3, const float* __restrict__ be3,
    const float* __restrict__ Wfc, const float* __restrict__ bfc,
    const float* __restrict__ Wd1, const float* __restrict__ bd1,
    const float* __restrict__ Wd2, const float* __restrict__ bd2,
    const float* __restrict__ Wd3, const float* __restrict__ bd3,
    float* __restrict__ out)
{
    __shared__ float S[7160];
    float* sWe1 = S;               // 2000
    float* sWe2 = S + 2000;        // 1200
    float* sWe3 = S + 3200;        // 600
    float* sWfc = S + 3800;        // 100
    float* sWd1 = S + 3900;        // 200
    float* sWd2 = S + 4100;        // 800
    float* sWd3 = S + 4900;        // 2000
    float* sbg  = S + 6900;
    float* sbe1 = S + 6950;
    float* sbe2 = S + 6990;
    float* sbe3 = S + 7020;
    float* sbfc = S + 7040;
    float* sbd1 = S + 7050;
    float* sbd2 = S + 7070;
    float* sbd3 = S + 7110;

    int tid = threadIdx.x;
    for (int j = tid; j < 2000; j += 128) sWe1[j] = We1[j];
    for (int j = tid; j < 1200; j += 128) sWe2[j] = We2[j];
    for (int j = tid; j <  600; j += 128) sWe3[j] = We3[j];
    for (int j = tid; j <  100; j += 128) sWfc[j] = Wfc[j];
    for (int j = tid; j <  200; j += 128) sWd1[j] = Wd1[j];
    for (int j = tid; j <  800; j += 128) sWd2[j] = Wd2[j];
    for (int j = tid; j < 2000; j += 128) sWd3[j] = Wd3[j];
    if (tid < 50) sbg[tid]  = bg[tid];
    if (tid < 40) sbe1[tid] = be1[tid];
    if (tid < 30) sbe2[tid] = be2[tid];
    if (tid < 20) sbe3[tid] = be3[tid];
    if (tid < 10) sbfc[tid] = bfc[tid];
    if (tid < 20) sbd1[tid] = bd1[tid];
    if (tid < 40) sbd2[tid] = bd2[tid];
    if (tid < 50) sbd3[tid] = bd3[tid];
    __syncthreads();

    int i = blockIdx.x * 128 + tid;
    if (i >= N_NODES) return;

    float dinv = rsqrtf((float)g_cnt[i] + 1.0f);
    const float4* aggr = (const float4*)(g_agg + (size_t)i * HPAD);
    const float4* h0r  = (const float4*)(g_h0s + (size_t)i * HPAD);

    float h[50];
#pragma unroll
    for (int j4 = 0; j4 < 12; j4++) {
        float4 a = aggr[j4], b = h0r[j4];
        h[4*j4+0] = fmaf(dinv, a.x + b.x, sbg[4*j4+0]);
        h[4*j4+1] = fmaf(dinv, a.y + b.y, sbg[4*j4+1]);
        h[4*j4+2] = fmaf(dinv, a.z + b.z, sbg[4*j4+2]);
        h[4*j4+3] = fmaf(dinv, a.w + b.w, sbg[4*j4+3]);
    }
    {
        float2 a = ((const float2*)aggr)[24], b = ((const float2*)h0r)[24];
        h[48] = fmaf(dinv, a.x + b.x, sbg[48]);
        h[49] = fmaf(dinv, a.y + b.y, sbg[49]);
    }

    float e1[40];
#pragma unroll
    for (int j = 0; j < 40; j++) {
        float a = sbe1[j];
#pragma unroll
        for (int k = 0; k < 50; k++) a = fmaf(h[k], sWe1[j * 50 + k], a);
        e1[j] = (a >= 0.0f) ? a : 0.01f * a;
    }

    float e2[30];
#pragma unroll
    for (int j = 0; j < 30; j++) {
        float a = sbe2[j];
#pragma unroll
        for (int k = 0; k < 40; k++) a = fmaf(e1[k], sWe2[j * 40 + k], a);
        e2[j] = (a >= 0.0f) ? a : 0.01f * a;
    }

    float e3[20];
#pragma unroll
    for (int j = 0; j < 20; j++) {
        float a = sbe3[j];
#pragma unroll
        for (int k = 0; k < 30; k++) a = fmaf(e2[k], sWe3[j * 30 + k], a);
        e3[j] = a;
    }

    float z1[10];
    {
        const float2* ep = (const float2*)(eps + (size_t)i * 10);
#pragma unroll
        for (int j2 = 0; j2 < 5; j2++) {
            float2 e2v = __ldg(&ep[j2]);
            z1[2*j2+0] = fmaf(e2v.x, __expf(0.5f * e3[10 + 2*j2+0]), e3[2*j2+0]);
            z1[2*j2+1] = fmaf(e2v.y, __expf(0.5f * e3[10 + 2*j2+1]), e3[2*j2+1]);
        }
    }

    float z[10];
#pragma unroll
    for (int j = 0; j < 10; j++) {
        float a = sbfc[j];
#pragma unroll
        for (int k = 0; k < 10; k++) a = fmaf(z1[k], sWfc[j * 10 + k], a);
        z[j] = fmaxf(a, 0.0f);
    }

    float d1[20];
#pragma unroll
    for (int j = 0; j < 20; j++) {
        float a = sbd1[j];
#pragma unroll
        for (int k = 0; k < 10; k++) a = fmaf(z[k], sWd1[j * 10 + k], a);
        d1[j] = (a >= 0.0f) ? a : 0.01f * a;
    }

    float d2[40];
#pragma unroll
    for (int j = 0; j < 40; j++) {
        float a = sbd2[j];
#pragma unroll
        for (int k = 0; k < 20; k++) a = fmaf(d1[k], sWd2[j * 20 + k], a);
        d2[j] = (a >= 0.0f) ? a : 0.01f * a;
    }

    float mpv[50];
#pragma unroll
    for (int j = 0; j < 50; j++) {
        float a = sbd3[j];
#pragma unroll
        for (int k = 0; k < 40; k++) a = fmaf(d2[k], sWd3[j * 40 + k], a);
        mpv[j] = 1.0f / (1.0f + __expf(-a));
    }

    // outputs: [mu_prime (N,50)][mu (N,10)][log_var (N,10)][z (N,10)]
    // NOTE: out row of 50 floats is only 8B-aligned (200*i) -> use float2 stores.
    float* mp = out + (size_t)i * 50;
#pragma unroll
    for (int j2 = 0; j2 < 25; j2++)
        ((float2*)mp)[j2] = make_float2(mpv[2*j2], mpv[2*j2+1]);

    float* omu = out + (size_t)N_NODES * 50 + (size_t)i * 10;
    float* olv = out + (size_t)N_NODES * 60 + (size_t)i * 10;
    float* oz  = out + (size_t)N_NODES * 70 + (size_t)i * 10;
#pragma unroll
    for (int j2 = 0; j2 < 5; j2++) {
        ((float2*)omu)[j2] = make_float2(e3[2*j2],      e3[2*j2+1]);
        ((float2*)olv)[j2] = make_float2(e3[10+2*j2],   e3[10+2*j2+1]);
        ((float2*)oz )[j2] = make_float2(z[2*j2],       z[2*j2+1]);
    }
}

// ---------------------------------------------------------------------------
extern "C" void kernel_launch(void* const* d_in, const int* in_sizes, int n_in,
                              void* d_out, int out_size) {
    const float* x   = (const float*)d_in[0];
    const int*   ei  = (const int*)d_in[1];
    const float* eps = (const float*)d_in[2];
    const float* Wg  = (const float*)d_in[3];
    const float* bg  = (const float*)d_in[4];
    const float* We1 = (const float*)d_in[5];
    const float* be1 = (const float*)d_in[6];
    const float* We2 = (const float*)d_in[7];
    const float* be2 = (const float*)d_in[8];
    const float* We3 = (const float*)d_in[9];
    const float* be3 = (const float*)d_in[10];
    const float* Wfc = (const float*)d_in[11];
    const float* bfc = (const float*)d_in[12];
    const float* Wd1 = (const float*)d_in[13];
    const float* bd1 = (const float*)d_in[14];
    const float* Wd2 = (const float*)d_in[15];
    const float* bd2 = (const float*)d_in[16];
    const float* Wd3 = (const float*)d_in[17];
    const float* bd3 = (const float*)d_in[18];
    float* out = (float*)d_out;

    k_zero<<<(N_NODES + 255) / 256, 256>>>();
    k_count<<<(N_EDGES + 255) / 256, 256>>>(ei);
    k_scan1<<<NB_SCAN, SCAN_B>>>();
    k_scan2<<<1, 256>>>();
    k_scan3<<<NB_SCAN, SCAN_B>>>();
    k_h0<<<(N_NODES + 127) / 128, 128>>>(x, Wg);
    k_fill<<<(N_EDGES + 255) / 256, 256>>>(ei);
    {
        long threads = (long)N_NODES * 13;
        k_gather<<<(int)((threads + 255) / 256), 256>>>();
    }
    k_dense<<<(N_NODES + 127) / 128, 128>>>(eps, bg, We1, be1, We2, be2, We3, be3,
                                            Wfc, bfc, Wd1, bd1, Wd2, bd2, Wd3, bd3, out);
    (void)in_sizes; (void)n_in; (void)out_size;
}

// round 5
// speedup vs baseline: 1.7606x; 1.1755x over previous
#include <cuda_runtime.h>
#include <cuda_fp16.h>
#include <math.h>

#define N_NODES 200000
#define N_EDGES 6400000
#define HPH 56             // halves per h0 row: 50 data + 6 pad = 112B, 16B aligned
#define AGGP 56            // floats per agg row (224B)
#define SCAN_B 1024
#define NB_SCAN 196        // ceil(200000/1024)

typedef unsigned long long ull;

// Scratch (device globals)
__device__ __half g_h0h[(size_t)N_NODES * HPH];  // dinv[src]-prescaled GCN features (fp16)
__device__ float  g_agg[(size_t)N_NODES * AGGP]; // gathered sums incl self (fp32)
__device__ int    g_cnt[N_NODES];                // in-degree (excl self)
__device__ int    g_off[N_NODES];                // scan offsets (mutated by fill)
__device__ int    g_bsums[NB_SCAN];
__device__ int    g_csr[N_EDGES];                // src ids bucketed by dst

// ---- f32x2 helpers --------------------------------------------------------
__device__ __forceinline__ ull pk(float lo, float hi) {
    ull r; asm("mov.b64 %0, {%1,%2};" : "=l"(r) : "f"(lo), "f"(hi)); return r;
}
__device__ __forceinline__ void upk(ull v, float& lo, float& hi) {
    asm("mov.b64 {%0,%1}, %2;" : "=f"(lo), "=f"(hi) : "l"(v));
}
__device__ __forceinline__ ull ffma2(ull a, ull b, ull c) {
    ull d; asm("fma.rn.f32x2 %0, %1, %2, %3;" : "=l"(d) : "l"(a), "l"(b), "l"(c));
    return d;
}

template<int IN>
__device__ __forceinline__ void packv(const float* v, ull* v2) {
#pragma unroll
    for (int k = 0; k < IN / 2; k++) v2[k] = pk(v[2 * k], v[2 * k + 1]);
}

// out[j] = b[j] + sum_k W[j,k] * in[k], via paired-k FFMA2 (bit-exact pairwise)
template<int OUT, int IN>
__device__ __forceinline__ void layer2(const float* __restrict__ W,
                                       const float* __restrict__ b,
                                       const ull* in2, float* out) {
#pragma unroll
    for (int j = 0; j < OUT; j++) {
        ull acc = 0ull;
        const ull* w = (const ull*)(W + j * IN);
#pragma unroll
        for (int k = 0; k < IN / 2; k++) acc = ffma2(in2[k], w[k], acc);
        float lo, hi; upk(acc, lo, hi);
        out[j] = lo + hi + b[j];
    }
}

// ---------------------------------------------------------------------------
__global__ void k_zero() {
    int i = blockIdx.x * blockDim.x + threadIdx.x;
    if (i < N_NODES) g_cnt[i] = 0;
}

__global__ void k_count(const int* __restrict__ ei) {
    int t = blockIdx.x * blockDim.x + threadIdx.x;
    if (t * 4 >= N_EDGES) return;
    int4 d = __ldg((const int4*)(ei + N_EDGES) + t);
    atomicAdd(&g_cnt[d.x], 1);
    atomicAdd(&g_cnt[d.y], 1);
    atomicAdd(&g_cnt[d.z], 1);
    atomicAdd(&g_cnt[d.w], 1);
}

// ---- 3-kernel exclusive scan of g_cnt into g_off --------------------------
__global__ __launch_bounds__(SCAN_B) void k_scan1() {
    __shared__ int s[SCAN_B];
    int tid = threadIdx.x;
    int i = blockIdx.x * SCAN_B + tid;
    int v = (i < N_NODES) ? g_cnt[i] : 0;
    s[tid] = v;
    __syncthreads();
#pragma unroll
    for (int off = 1; off < SCAN_B; off <<= 1) {
        int t = (tid >= off) ? s[tid - off] : 0;
        __syncthreads();
        s[tid] += t;
        __syncthreads();
    }
    if (i < N_NODES) g_off[i] = s[tid] - v;
    if (tid == SCAN_B - 1) g_bsums[blockIdx.x] = s[tid];
}

__global__ __launch_bounds__(256) void k_scan2() {
    __shared__ int s[256];
    int tid = threadIdx.x;
    int v = (tid < NB_SCAN) ? g_bsums[tid] : 0;
    s[tid] = v;
    __syncthreads();
#pragma unroll
    for (int off = 1; off < 256; off <<= 1) {
        int t = (tid >= off) ? s[tid - off] : 0;
        __syncthreads();
        s[tid] += t;
        __syncthreads();
    }
    if (tid < NB_SCAN) g_bsums[tid] = s[tid] - v;
}

__global__ __launch_bounds__(SCAN_B) void k_scan3() {
    int i = blockIdx.x * SCAN_B + threadIdx.x;
    if (i < N_NODES) g_off[i] += g_bsums[blockIdx.x];
}

// ---- CSR fill -------------------------------------------------------------
__global__ void k_fill(const int* __restrict__ ei) {
    int t = blockIdx.x * blockDim.x + threadIdx.x;
    if (t * 4 >= N_EDGES) return;
    int4 s = __ldg((const int4*)ei + t);
    int4 d = __ldg((const int4*)(ei + N_EDGES) + t);
    g_csr[atomicAdd(&g_off[d.x], 1)] = s.x;
    g_csr[atomicAdd(&g_off[d.y], 1)] = s.y;
    g_csr[atomicAdd(&g_off[d.z], 1)] = s.z;
    g_csr[atomicAdd(&g_off[d.w], 1)] = s.w;
}

// ---------------------------------------------------------------------------
// h0h[i] = fp16( (x[i,100:150] @ Wg^T) * rsqrt(cnt[i]+1) )
// ---------------------------------------------------------------------------
__global__ __launch_bounds__(128) void k_h0(const float* __restrict__ x,
                                            const float* __restrict__ Wg) {
    __shared__ float Ws[2500];
    int tid = threadIdx.x;
    for (int j = tid; j < 2500; j += 128) Ws[j] = Wg[j];
    __syncthreads();
    int i = blockIdx.x * 128 + tid;
    if (i >= N_NODES) return;

    ull x2[25];
    const float2* xr = (const float2*)(x + (size_t)i * 150 + 100);
#pragma unroll
    for (int k2 = 0; k2 < 25; k2++) {
        float2 v = __ldg(&xr[k2]);
        x2[k2] = pk(v.x, v.y);
    }
    float dinv = rsqrtf((float)g_cnt[i] + 1.0f);

    unsigned int u[25];
#pragma unroll
    for (int j2 = 0; j2 < 25; j2++) {
        ull a0 = 0ull, a1 = 0ull;
        const ull* w0 = (const ull*)(Ws + (2 * j2) * 50);
        const ull* w1 = (const ull*)(Ws + (2 * j2 + 1) * 50);
#pragma unroll
        for (int k2 = 0; k2 < 25; k2++) {
            a0 = ffma2(x2[k2], w0[k2], a0);
            a1 = ffma2(x2[k2], w1[k2], a1);
        }
        float l0, h0v, l1, h1v;
        upk(a0, l0, h0v); upk(a1, l1, h1v);
        __half2 hv = __floats2half2_rn((l0 + h0v) * dinv, (l1 + h1v) * dinv);
        u[j2] = *(unsigned int*)&hv;
    }
    uint4* orow = (uint4*)(g_h0h + (size_t)i * HPH);
#pragma unroll
    for (int q = 0; q < 6; q++)
        orow[q] = make_uint4(u[4*q], u[4*q+1], u[4*q+2], u[4*q+3]);
    ((unsigned int*)orow)[24] = u[24];
    ((unsigned int*)orow)[25] = 0;   // pad halves 50..53
    ((unsigned int*)orow)[26] = 0;
    ((unsigned int*)orow)[27] = 0;   // pad halves 54..55
}

// ---------------------------------------------------------------------------
// Gather: 7 threads per node, each owning one 16B (8-half) chunk.
// acc initialized from the node's own row (self loop folded in).
// ---------------------------------------------------------------------------
__device__ __forceinline__ void add8(uint4 w, float* a) {
    float2 f0 = __half22float2(*(__half2*)&w.x);
    float2 f1 = __half22float2(*(__half2*)&w.y);
    float2 f2 = __half22float2(*(__half2*)&w.z);
    float2 f3 = __half22float2(*(__half2*)&w.w);
    a[0] += f0.x; a[1] += f0.y; a[2] += f1.x; a[3] += f1.y;
    a[4] += f2.x; a[5] += f2.y; a[6] += f3.x; a[7] += f3.y;
}

__global__ __launch_bounds__(224) void k_gather() {
    int t = blockIdx.x * 224 + threadIdx.x;
    int i = t / 7;
    if (i >= N_NODES) return;
    int c = t - i * 7;
    int start = (i == 0) ? 0 : __ldg(&g_off[i - 1]);
    int end = __ldg(&g_off[i]);

    const uint4* base = (const uint4*)g_h0h;   // 7 uint4 per row
    float acc[8] = {0,0,0,0,0,0,0,0};
    add8(__ldg(&base[(size_t)i * 7 + c]), acc);   // self term

    int p = start;
    for (; p + 3 < end; p += 4) {
        int s0 = __ldg(&g_csr[p]);
        int s1 = __ldg(&g_csr[p + 1]);
        int s2 = __ldg(&g_csr[p + 2]);
        int s3 = __ldg(&g_csr[p + 3]);
        uint4 w0 = __ldg(&base[(size_t)s0 * 7 + c]);
        uint4 w1 = __ldg(&base[(size_t)s1 * 7 + c]);
        uint4 w2 = __ldg(&base[(size_t)s2 * 7 + c]);
        uint4 w3 = __ldg(&base[(size_t)s3 * 7 + c]);
        add8(w0, acc); add8(w1, acc); add8(w2, acc); add8(w3, acc);
    }
    for (; p < end; p++) {
        add8(__ldg(&base[(size_t)__ldg(&g_csr[p]) * 7 + c]), acc);
    }
    float4* o = (float4*)(g_agg + (size_t)i * AGGP + 8 * c);
    o[0] = make_float4(acc[0], acc[1], acc[2], acc[3]);
    o[1] = make_float4(acc[4], acc[5], acc[6], acc[7]);
}

// ---------------------------------------------------------------------------
// Fused finalize + full VAE chain, one thread per node. f32x2 throughout.
// ---------------------------------------------------------------------------
__global__ __launch_bounds__(128) void k_dense(
    const float* __restrict__ eps,
    const float* __restrict__ bg,
    const float* __restrict__ We1, const float* __restrict__ be1,
    const float* __restrict__ We2, const float* __restrict__ be2,
    const float* __restrict__ We3, const float* __restrict__ be3,
    const float* __restrict__ Wfc, const float* __restrict__ bfc,
    const float* __restrict__ Wd1, const float* __restrict__ bd1,
    const float* __restrict__ Wd2, const float* __restrict__ bd2,
    const float* __restrict__ Wd3, const float* __restrict__ bd3,
    float* __restrict__ out)
{
    __shared__ float S[7160];
    float* sWe1 = S;               // 2000
    float* sWe2 = S + 2000;        // 1200
    float* sWe3 = S + 3200;        // 600
    float* sWfc = S + 3800;        // 100
    float* sWd1 = S + 3900;        // 200
    float* sWd2 = S + 4100;        // 800
    float* sWd3 = S + 4900;        // 2000
    float* sbg  = S + 6900;
    float* sbe1 = S + 6950;
    float* sbe2 = S + 6990;
    float* sbe3 = S + 7020;
    float* sbfc = S + 7040;
    float* sbd1 = S + 7050;
    float* sbd2 = S + 7070;
    float* sbd3 = S + 7110;

    int tid = threadIdx.x;
    for (int j = tid; j < 2000; j += 128) sWe1[j] = We1[j];
    for (int j = tid; j < 1200; j += 128) sWe2[j] = We2[j];
    for (int j = tid; j <  600; j += 128) sWe3[j] = We3[j];
    for (int j = tid; j <  100; j += 128) sWfc[j] = Wfc[j];
    for (int j = tid; j <  200; j += 128) sWd1[j] = Wd1[j];
    for (int j = tid; j <  800; j += 128) sWd2[j] = Wd2[j];
    for (int j = tid; j < 2000; j += 128) sWd3[j] = Wd3[j];
    if (tid < 50) sbg[tid]  = bg[tid];
    if (tid < 40) sbe1[tid] = be1[tid];
    if (tid < 30) sbe2[tid] = be2[tid];
    if (tid < 20) sbe3[tid] = be3[tid];
    if (tid < 10) sbfc[tid] = bfc[tid];
    if (tid < 20) sbd1[tid] = bd1[tid];
    if (tid < 40) sbd2[tid] = bd2[tid];
    if (tid < 50) sbd3[tid] = bd3[tid];
    __syncthreads();

    int i = blockIdx.x * 128 + tid;
    if (i >= N_NODES) return;

    float dinv = rsqrtf((float)g_cnt[i] + 1.0f);
    const float4* aggr = (const float4*)(g_agg + (size_t)i * AGGP);

    float h[52];
#pragma unroll
    for (int j4 = 0; j4 < 13; j4++) {
        float4 a = __ldg(&aggr[j4]);
        h[4*j4+0] = a.x; h[4*j4+1] = a.y; h[4*j4+2] = a.z; h[4*j4+3] = a.w;
    }
#pragma unroll
    for (int j = 0; j < 50; j++) h[j] = fmaf(dinv, h[j], sbg[j]);

    ull h2[25];  packv<50>(h, h2);
    float e1[40];
    layer2<40, 50>(sWe1, sbe1, h2, e1);
#pragma unroll
    for (int j = 0; j < 40; j++) e1[j] = (e1[j] >= 0.0f) ? e1[j] : 0.01f * e1[j];

    ull e1p[20]; packv<40>(e1, e1p);
    float e2[30];
    layer2<30, 40>(sWe2, sbe2, e1p, e2);
#pragma unroll
    for (int j = 0; j < 30; j++) e2[j] = (e2[j] >= 0.0f) ? e2[j] : 0.01f * e2[j];

    ull e2p[15]; packv<30>(e2, e2p);
    float e3[20];
    layer2<20, 30>(sWe3, sbe3, e2p, e3);   // no activation

    float z1[10];
    {
        const float2* ep = (const float2*)(eps + (size_t)i * 10);
#pragma unroll
        for (int j2 = 0; j2 < 5; j2++) {
            float2 ev = __ldg(&ep[j2]);
            z1[2*j2+0] = fmaf(ev.x, __expf(0.5f * e3[10 + 2*j2+0]), e3[2*j2+0]);
            z1[2*j2+1] = fmaf(ev.y, __expf(0.5f * e3[10 + 2*j2+1]), e3[2*j2+1]);
        }
    }

    ull z1p[5]; packv<10>(z1, z1p);
    float z[10];
    layer2<10, 10>(sWfc, sbfc, z1p, z);
#pragma unroll
    for (int j = 0; j < 10; j++) z[j] = fmaxf(z[j], 0.0f);

    ull zp[5]; packv<10>(z, zp);
    float d1[20];
    layer2<20, 10>(sWd1, sbd1, zp, d1);
#pragma unroll
    for (int j = 0; j < 20; j++) d1[j] = (d1[j] >= 0.0f) ? d1[j] : 0.01f * d1[j];

    ull d1p[10]; packv<20>(d1, d1p);
    float d2[40];
    layer2<40, 20>(sWd2, sbd2, d1p, d2);
#pragma unroll
    for (int j = 0; j < 40; j++) d2[j] = (d2[j] >= 0.0f) ? d2[j] : 0.01f * d2[j];

    ull d2p[20]; packv<40>(d2, d2p);
    float mpv[50];
    layer2<50, 40>(sWd3, sbd3, d2p, mpv);
#pragma unroll
    for (int j = 0; j < 50; j++) mpv[j] = 1.0f / (1.0f + __expf(-mpv[j]));

    // outputs: [mu_prime (N,50)][mu (N,10)][log_var (N,10)][z (N,10)]
    // out row of 50 floats is only 8B-aligned -> float2 stores.
    float* mp = out + (size_t)i * 50;
#pragma unroll
    for (int j2 = 0; j2 < 25; j2++)
        ((float2*)mp)[j2] = make_float2(mpv[2*j2], mpv[2*j2+1]);

    float* omu = out + (size_t)N_NODES * 50 + (size_t)i * 10;
    float* olv = out + (size_t)N_NODES * 60 + (size_t)i * 10;
    float* oz  = out + (size_t)N_NODES * 70 + (size_t)i * 10;
#pragma unroll
    for (int j2 = 0; j2 < 5; j2++) {
        ((float2*)omu)[j2] = make_float2(e3[2*j2],    e3[2*j2+1]);
        ((float2*)olv)[j2] = make_float2(e3[10+2*j2], e3[10+2*j2+1]);
        ((float2*)oz )[j2] = make_float2(z[2*j2],     z[2*j2+1]);
    }
}

// ---------------------------------------------------------------------------
extern "C" void kernel_launch(void* const* d_in, const int* in_sizes, int n_in,
                              void* d_out, int out_size) {
    const float* x   = (const float*)d_in[0];
    const int*   ei  = (const int*)d_in[1];
    const float* eps = (const float*)d_in[2];
    const float* Wg  = (const float*)d_in[3];
    const float* bg  = (const float*)d_in[4];
    const float* We1 = (const float*)d_in[5];
    const float* be1 = (const float*)d_in[6];
    const float* We2 = (const float*)d_in[7];
    const float* be2 = (const float*)d_in[8];
    const float* We3 = (const float*)d_in[9];
    const float* be3 = (const float*)d_in[10];
    const float* Wfc = (const float*)d_in[11];
    const float* bfc = (const float*)d_in[12];
    const float* Wd1 = (const float*)d_in[13];
    const float* bd1 = (const float*)d_in[14];
    const float* Wd2 = (const float*)d_in[15];
    const float* bd2 = (const float*)d_in[16];
    const float* Wd3 = (const float*)d_in[17];
    const float* bd3 = (const float*)d_in[18];
    float* out = (float*)d_out;

    k_zero<<<(N_NODES + 255) / 256, 256>>>();
    k_count<<<(N_EDGES / 4 + 255) / 256, 256>>>(ei);
    k_scan1<<<NB_SCAN, SCAN_B>>>();
    k_scan2<<<1, 256>>>();
    k_scan3<<<NB_SCAN, SCAN_B>>>();
    k_h0<<<(N_NODES + 127) / 128, 128>>>(x, Wg);
    k_fill<<<(N_EDGES / 4 + 255) / 256, 256>>>(ei);
    {
        long threads = (long)N_NODES * 7;
        k_gather<<<(int)((threads + 223) / 224), 224>>>();
    }
    k_dense<<<(N_NODES + 127) / 128, 128>>>(eps, bg, We1, be1, We2, be2, We3, be3,
                                            Wfc, bfc, Wd1, bd1, Wd2, bd2, Wd3, bd3, out);
    (void)in_sizes; (void)n_in; (void)out_size;
}